// round 11
// baseline (speedup 1.0000x reference)
#include <cuda_runtime.h>
#include <cuda_fp16.h>
#include <cstdint>

// ---------------------------------------------------------------------------
// PairInteractionGrid (sm_103a) R10 — HMMA fp16 2-pass split.
//   A split: A = Ah + Al (both fp16, exact to ~2^-22).
//   W rounded once to fp16 (residual 2^-11, dropped).
//   Two MMA passes per GEMM: Ah@Wh + Al@Wh   (fp32 accumulate).
//   p  = price @ W_p + b_p ; v = liquid @ W_v + b_v          (k_pre)
//   A  = p @ W1p ; Bv = v @ W1v + b1                          (k_pre)
//   z(n,m) = A_n + Bv_m + (p*v)@Wc + |p-v|@Wd                 (k_pair)
//   out = silu(z) @ W2 + b2                                   (k_pair)
// ---------------------------------------------------------------------------

typedef unsigned int u32;
#define DI __device__ __forceinline__

DI float silu_f(float x) { return __fdividef(x, 1.0f + __expf(-x)); }

DI u32 cvtH2(float f0, float f1) {   // f0 -> low half fp16x2
    u32 r; asm("cvt.rn.f16x2.f32 %0, %1, %2;" : "=r"(r) : "f"(f1), "f"(f0)); return r;
}
DI void unpkH2(u32 h, float& f0, float& f1) {
    asm("{\n\t.reg .f16 lo, hi;\n\t"
        "mov.b32 {lo, hi}, %2;\n\t"
        "cvt.f32.f16 %0, lo;\n\t"
        "cvt.f32.f16 %1, hi;\n\t}"
        : "=f"(f0), "=f"(f1) : "r"(h));
}
DI void splitH2(float f0, float f1, u32& h, u32& l) {
    h = cvtH2(f0, f1);
    float h0, h1;
    unpkH2(h, h0, h1);
    l = cvtH2(f0 - h0, f1 - h1);
}
DI void hmma(float* c, const u32* a, u32 b0, u32 b1) {
    asm("mma.sync.aligned.m16n8k16.row.col.f32.f16.f16.f32 "
        "{%0,%1,%2,%3},{%4,%5,%6,%7},{%8,%9},{%0,%1,%2,%3};"
        : "+f"(c[0]), "+f"(c[1]), "+f"(c[2]), "+f"(c[3])
        : "r"(a[0]), "r"(a[1]), "r"(a[2]), "r"(a[3]), "r"(b0), "r"(b1));
}

// ------------------------- global scratch ----------------------------------
// B=4 T=64 N=32 M=32 D=128 ; BT=256 ; units=2048 ; bands=16384 (16 rows each)
__device__ __align__(16) float g_p [8192 * 128];   // p[row][d]   row=bt*32+n
__device__ __align__(16) float g_A [8192 * 128];   // A[row][k]
__device__ __align__(16) float g_v [8192 * 128];   // v[row][d]   row=bt*32+m
__device__ __align__(16) float g_Bv[8192 * 128];   // Bv[row][k]  (b1 folded)
// fp16 hi-only images: [mat][n][sj] uint2 { h(k0,k1), h(k8,k9) }
// mat: 0 Wc, 1 Wd, 2 W2, 3 W_p, 4 W_v, 5 W1p, 6 W1v ; sj = 4s+j ; k0 = 16s+2j
#define IMG2_S 36                   // uint2 stride per n (conflict-free LDS.64)
#define IMG2   (128 * IMG2_S)       // 4608 uint2 per image (36,864 B)
__device__ __align__(16) uint2 g_img2[7 * IMG2];

// ---------------------------------------------------------------------------
// Kernel 1: weight prep (fp16 round) into images. grid (7,16) x 256.
// ---------------------------------------------------------------------------
__global__ void __launch_bounds__(256) k_wprep(const float* __restrict__ W_p,
                                               const float* __restrict__ W_v,
                                               const float* __restrict__ W1,
                                               const float* __restrict__ W2)
{
    const int mat = blockIdx.x;
    const float* src =
        (mat == 0) ? (W1 + 256 * 128) :
        (mat == 1) ? (W1 + 384 * 128) :
        (mat == 2) ? W2 :
        (mat == 3) ? W_p :
        (mat == 4) ? W_v :
        (mat == 5) ? W1 : (W1 + 128 * 128);
    const int pos = blockIdx.y * 256 + threadIdx.x;   // 0..4095
    const int n  = pos & 127;
    const int sj = pos >> 7;
    const int s  = sj >> 2, j = sj & 3;
    const int ka = 16 * s + 2 * j;
    u32 h0 = cvtH2(__ldg(src + ka * 128 + n),       __ldg(src + (ka + 1) * 128 + n));
    u32 h1 = cvtH2(__ldg(src + (ka + 8) * 128 + n), __ldg(src + (ka + 9) * 128 + n));
    g_img2[mat * IMG2 + n * IMG2_S + sj] = make_uint2(h0, h1);
}

// ---------------------------------------------------------------------------
// Kernel 2: HMMA precompute of p, v, A, Bv. grid (128, 2) x 128 thr, 2 CTA/SM.
// Block = 64 rows of one path; warp = 16 rows x 128 cols. Weights via __ldg
// streams (no smem, no barriers). 2-pass fp16, depth-8 interleave.
// ---------------------------------------------------------------------------
__global__ void __launch_bounds__(128, 2) k_pre_mma(
    const float* __restrict__ price, const float* __restrict__ liquid,
    const float* __restrict__ b_p,   const float* __restrict__ b_v,
    const float* __restrict__ b1)
{
    const int path = blockIdx.y;
    const int r0   = blockIdx.x * 64;
    const float* X  = path ? liquid : price;
    const float* bi = path ? b_v : b_p;
    const uint2* imgW  = g_img2 + (3 + path) * IMG2;   // W_p / W_v
    const uint2* imgW1 = g_img2 + (5 + path) * IMG2;   // W1p / W1v
    float* dstY = path ? g_v  : g_p;
    float* dstZ = path ? g_Bv : g_A;

    const int tid  = threadIdx.x;
    const int w    = tid >> 5;
    const int lane = tid & 31;
    const int g    = lane >> 2;
    const int j    = lane & 3;

    // ---- load X A-fragments (fp16 split) ----
    const int ra = r0 + w * 16 + g;
    const int rb = ra + 8;
    u32 Xh[8][4], Xl[8][4];
#pragma unroll
    for (int s = 0; s < 8; s++) {
        const int ka = 16 * s + 2 * j;
        float2 xa0 = *(const float2*)(X + (size_t)ra * 128 + ka);
        float2 xb0 = *(const float2*)(X + (size_t)rb * 128 + ka);
        float2 xa1 = *(const float2*)(X + (size_t)ra * 128 + ka + 8);
        float2 xb1 = *(const float2*)(X + (size_t)rb * 128 + ka + 8);
        splitH2(xa0.x, xa0.y, Xh[s][0], Xl[s][0]);
        splitH2(xb0.x, xb0.y, Xh[s][1], Xl[s][1]);
        splitH2(xa1.x, xa1.y, Xh[s][2], Xl[s][2]);
        splitH2(xb1.x, xb1.y, Xh[s][3], Xl[s][3]);
    }

    // ---- GEMM1: Y = X @ Wi (2-pass, depth-8) ----
    float yacc[16][4];
#pragma unroll
    for (int nt = 0; nt < 16; nt++)
#pragma unroll
        for (int q = 0; q < 4; q++) yacc[nt][q] = 0.0f;
#pragma unroll
    for (int s = 0; s < 8; s++)
#pragma unroll
        for (int q = 0; q < 2; q++) {
            uint2 wv[8];
#pragma unroll
            for (int t = 0; t < 8; t++)
                wv[t] = __ldg(imgW + (8 * (8 * q + t) + g) * IMG2_S + 4 * s + j);
#pragma unroll
            for (int t = 0; t < 8; t++) hmma(yacc[8 * q + t], Xh[s], wv[t].x, wv[t].y);
#pragma unroll
            for (int t = 0; t < 8; t++) hmma(yacc[8 * q + t], Xl[s], wv[t].x, wv[t].y);
        }

    // ---- epilogue 1: + bias, store Y, re-split as GEMM2 A-frags ----
#pragma unroll
    for (int nt = 0; nt < 16; nt++) {
        const int c = 8 * nt + 2 * j;
        const float bb0 = __ldg(bi + c), bb1 = __ldg(bi + c + 1);
        float y0 = yacc[nt][0] + bb0, y1 = yacc[nt][1] + bb1;
        float y2 = yacc[nt][2] + bb0, y3 = yacc[nt][3] + bb1;
        *(float2*)(dstY + (size_t)ra * 128 + c) = make_float2(y0, y1);
        *(float2*)(dstY + (size_t)rb * 128 + c) = make_float2(y2, y3);
        const int s2 = nt >> 1, o = (nt & 1) * 2;
        splitH2(y0, y1, Xh[s2][o],     Xl[s2][o]);
        splitH2(y2, y3, Xh[s2][o + 1], Xl[s2][o + 1]);
    }

    // ---- GEMM2: Z = Y @ W1x (2-pass, depth-8) ----
    float zacc[16][4];
#pragma unroll
    for (int nt = 0; nt < 16; nt++)
#pragma unroll
        for (int q = 0; q < 4; q++) zacc[nt][q] = 0.0f;
#pragma unroll
    for (int s = 0; s < 8; s++)
#pragma unroll
        for (int q = 0; q < 2; q++) {
            uint2 wv[8];
#pragma unroll
            for (int t = 0; t < 8; t++)
                wv[t] = __ldg(imgW1 + (8 * (8 * q + t) + g) * IMG2_S + 4 * s + j);
#pragma unroll
            for (int t = 0; t < 8; t++) hmma(zacc[8 * q + t], Xh[s], wv[t].x, wv[t].y);
#pragma unroll
            for (int t = 0; t < 8; t++) hmma(zacc[8 * q + t], Xl[s], wv[t].x, wv[t].y);
        }

    // ---- epilogue 2: (+ b1 on liquid path), store Z ----
#pragma unroll
    for (int nt = 0; nt < 16; nt++) {
        const int c = 8 * nt + 2 * j;
        const float bb0 = path ? __ldg(b1 + c)     : 0.0f;
        const float bb1 = path ? __ldg(b1 + c + 1) : 0.0f;
        *(float2*)(dstZ + (size_t)ra * 128 + c) =
            make_float2(zacc[nt][0] + bb0, zacc[nt][1] + bb1);
        *(float2*)(dstZ + (size_t)rb * 128 + c) =
            make_float2(zacc[nt][2] + bb0, zacc[nt][3] + bb1);
    }
}

// ---------------------------------------------------------------------------
// Kernel 3: pair kernel — 148 x 256 thr, 8 independent warps/CTA.
// Band = 16 pair-rows x 128 cols; 16384 bands over 1184 warps, contiguous.
// smem: Wc+Wd+W2 fp16 images (110.6 KB) + b2 ; v/Bv/p/A via L1 __ldg.
// 2-pass fp16, depth-8 interleave, no loop barriers.
// ---------------------------------------------------------------------------
__global__ void __launch_bounds__(256, 1) k_pair_mma(const float* __restrict__ b2,
                                                     float* __restrict__ out)
{
    extern __shared__ __align__(16) char smem[];
    uint2* sC  = (uint2*)smem;                      // Wc
    uint2* sD  = sC + IMG2;                         // Wd
    uint2* sW2 = sD + IMG2;                         // W2
    float* sB2 = (float*)(sW2 + IMG2);              // [128]

    const int tid  = threadIdx.x;
    const int w    = tid >> 5;
    const int lane = tid & 31;
    const int g    = lane >> 2;
    const int j    = lane & 3;

    for (int i = tid; i < 3 * IMG2; i += 256) ((uint2*)sC)[i] = g_img2[i];
    for (int i = tid; i < 128; i += 256) sB2[i] = b2[i];
    __syncthreads();

    const int gw   = blockIdx.x * 8 + w;            // 0..1183
    const int b_lo = (int)(((long long)gw * 16384) / 1184);
    const int b_hi = (int)(((long long)(gw + 1) * 16384) / 1184);

    for (int b = b_lo; b < b_hi; b++) {
        const int bt   = b >> 6;
        const int tile = (b >> 3) & 7;
        const int rb   = b & 7;
        const int ln   = rb >> 1;
        const int mlo  = (rb & 1) * 16 + g;
        const int mhi  = mlo + 8;
        const float* prow = g_p  + (size_t)(bt * 32 + tile * 4 + ln) * 128;
        const float* arow = g_A  + (size_t)(bt * 32 + tile * 4 + ln) * 128;
        const float* vlo  = g_v  + (size_t)(bt * 32 + mlo) * 128;
        const float* vhi  = g_v  + (size_t)(bt * 32 + mhi) * 128;
        const float* bvlo = g_Bv + (size_t)(bt * 32 + mlo) * 128;
        const float* bvhi = g_Bv + (size_t)(bt * 32 + mhi) * 128;

        // ---- layer 1: acc = (p*v)@Wc + |p-v|@Wd (2-pass, depth-8) ----
        float acc[16][4];
#pragma unroll
        for (int nt = 0; nt < 16; nt++)
#pragma unroll
            for (int q = 0; q < 4; q++) acc[nt][q] = 0.0f;

#pragma unroll
        for (int s = 0; s < 8; s++) {
            const int d0 = 16 * s + 2 * j;
            float2 pa  = *(const float2*)(prow + d0);
            float2 pb  = *(const float2*)(prow + d0 + 8);
            float2 va0 = __ldg((const float2*)(vlo + d0));
            float2 vb0 = __ldg((const float2*)(vhi + d0));
            float2 va8 = __ldg((const float2*)(vlo + d0 + 8));
            float2 vb8 = __ldg((const float2*)(vhi + d0 + 8));
            u32 Ph[4], Pl[4], Qh[4], Ql[4];
            splitH2(pa.x * va0.x, pa.y * va0.y, Ph[0], Pl[0]);
            splitH2(pa.x * vb0.x, pa.y * vb0.y, Ph[1], Pl[1]);
            splitH2(pb.x * va8.x, pb.y * va8.y, Ph[2], Pl[2]);
            splitH2(pb.x * vb8.x, pb.y * vb8.y, Ph[3], Pl[3]);
            splitH2(fabsf(pa.x - va0.x), fabsf(pa.y - va0.y), Qh[0], Ql[0]);
            splitH2(fabsf(pa.x - vb0.x), fabsf(pa.y - vb0.y), Qh[1], Ql[1]);
            splitH2(fabsf(pb.x - va8.x), fabsf(pb.y - va8.y), Qh[2], Ql[2]);
            splitH2(fabsf(pb.x - vb8.x), fabsf(pb.y - vb8.y), Qh[3], Ql[3]);
#pragma unroll
            for (int q = 0; q < 2; q++) {
                uint2 cv[8];
#pragma unroll
                for (int t = 0; t < 8; t++)
                    cv[t] = sC[(8 * (8 * q + t) + g) * IMG2_S + 4 * s + j];
#pragma unroll
                for (int t = 0; t < 8; t++) hmma(acc[8 * q + t], Ph, cv[t].x, cv[t].y);
#pragma unroll
                for (int t = 0; t < 8; t++) hmma(acc[8 * q + t], Pl, cv[t].x, cv[t].y);
                uint2 dv[8];
#pragma unroll
                for (int t = 0; t < 8; t++)
                    dv[t] = sD[(8 * (8 * q + t) + g) * IMG2_S + 4 * s + j];
#pragma unroll
                for (int t = 0; t < 8; t++) hmma(acc[8 * q + t], Qh, dv[t].x, dv[t].y);
#pragma unroll
                for (int t = 0; t < 8; t++) hmma(acc[8 * q + t], Ql, dv[t].x, dv[t].y);
            }
        }

        // ---- epilogue 1: z = acc + A + Bv ; H = silu(z) as reg A-frags ----
        u32 Hh[8][4], Hl[8][4];
#pragma unroll
        for (int nt = 0; nt < 16; nt++) {
            int col = 8 * nt + 2 * j;
            float2 a2 = *(const float2*)(arow + col);
            float2 bl = __ldg((const float2*)(bvlo + col));
            float2 bh = __ldg((const float2*)(bvhi + col));
            float z0 = acc[nt][0] + a2.x + bl.x;
            float z1 = acc[nt][1] + a2.y + bl.y;
            float z2 = acc[nt][2] + a2.x + bh.x;
            float z3 = acc[nt][3] + a2.y + bh.y;
            int s2 = nt >> 1, o = (nt & 1) * 2;
            splitH2(silu_f(z0), silu_f(z1), Hh[s2][o],     Hl[s2][o]);
            splitH2(silu_f(z2), silu_f(z3), Hh[s2][o + 1], Hl[s2][o + 1]);
        }

        // ---- layer 2: out = H @ W2 (2-pass, depth-8, smem) ----
        float ac2[16][4];
#pragma unroll
        for (int nt = 0; nt < 16; nt++)
#pragma unroll
            for (int q = 0; q < 4; q++) ac2[nt][q] = 0.0f;

#pragma unroll
        for (int s = 0; s < 8; s++)
#pragma unroll
            for (int q = 0; q < 2; q++) {
                uint2 wv[8];
#pragma unroll
                for (int t = 0; t < 8; t++)
                    wv[t] = sW2[(8 * (8 * q + t) + g) * IMG2_S + 4 * s + j];
#pragma unroll
                for (int t = 0; t < 8; t++) hmma(ac2[8 * q + t], Hh[s], wv[t].x, wv[t].y);
#pragma unroll
                for (int t = 0; t < 8; t++) hmma(ac2[8 * q + t], Hl[s], wv[t].x, wv[t].y);
            }

        // ---- epilogue 2: + b2, store ----
        const int u = bt * 8 + tile;
        float* ob = out + ((size_t)u * 128 + ln * 32) * 128;
#pragma unroll
        for (int nt = 0; nt < 16; nt++) {
            int col = 8 * nt + 2 * j;
            float bb0 = sB2[col], bb1 = sB2[col + 1];
            *(float2*)(ob + (size_t)mlo * 128 + col) =
                make_float2(ac2[nt][0] + bb0, ac2[nt][1] + bb1);
            *(float2*)(ob + (size_t)mhi * 128 + col) =
                make_float2(ac2[nt][2] + bb0, ac2[nt][3] + bb1);
        }
    }
}

// ---------------------------------------------------------------------------
extern "C" void kernel_launch(void* const* d_in, const int* in_sizes, int n_in,
                              void* d_out, int out_size)
{
    const float* price  = (const float*)d_in[0];
    const float* liquid = (const float*)d_in[1];
    const float* W_p = (const float*)d_in[2];
    const float* b_p = (const float*)d_in[3];
    const float* W_v = (const float*)d_in[4];
    const float* b_v = (const float*)d_in[5];
    const float* W1  = (const float*)d_in[6];
    const float* b1  = (const float*)d_in[7];
    const float* W2  = (const float*)d_in[8];
    const float* b2  = (const float*)d_in[9];
    float* out = (float*)d_out;

    const size_t sm2 = 3 * IMG2 * 8 + 128 * 4;        // 111,104
    cudaFuncSetAttribute(k_pair_mma, cudaFuncAttributeMaxDynamicSharedMemorySize, (int)sm2);

    k_wprep<<<dim3(7, 16), 256>>>(W_p, W_v, W1, W2);
    k_pre_mma<<<dim3(128, 2), 128>>>(price, liquid, b_p, b_v, b1);
    k_pair_mma<<<148, 256, sm2>>>(b2, out);
}

// round 12
// speedup vs baseline: 1.4373x; 1.4373x over previous
#include <cuda_runtime.h>
#include <cuda_fp16.h>
#include <cstdint>

// ---------------------------------------------------------------------------
// PairInteractionGrid (sm_103a) R12 — HMMA fp16 2-pass, Veltkamp split.
//   A = Ah + Al (Ah = 11-bit Veltkamp head, exact in fp16; Al residual).
//   W rounded once to fp16. Two MMA passes per GEMM: Ah@Wh + Al@Wh (fp32 acc).
//   p  = price @ W_p + b_p ; v = liquid @ W_v + b_v          (k_pre)
//   A  = p @ W1p ; Bv = v @ W1v + b1                          (k_pre)
//   z(n,m) = A_n + Bv_m + (p*v)@Wc + |p-v|@Wd                 (k_pair)
//   out = silu(z) @ W2 + b2                                   (k_pair)
// ---------------------------------------------------------------------------

typedef unsigned int u32;
#define DI __device__ __forceinline__

DI float silu_f(float x) { return __fdividef(x, 1.0f + __expf(-x)); }

DI u32 cvtH2(float f0, float f1) {   // f0 -> low half fp16x2
    u32 r; asm("cvt.rn.f16x2.f32 %0, %1, %2;" : "=r"(r) : "f"(f1), "f"(f0)); return r;
}
// Veltkamp split at 11 significand bits: h exact in fp16, l = exact residual.
// Pure fp32 ALU (rt-2 class) — no scalar F2F converts on the critical path.
DI void splitH2(float f0, float f1, u32& h, u32& l) {
    const float S = 8193.0f;               // 2^13 + 1
    float c0 = __fmul_rn(S, f0);
    float d0 = __fsub_rn(c0, f0);
    float h0 = __fsub_rn(c0, d0);
    float l0 = __fsub_rn(f0, h0);
    float c1 = __fmul_rn(S, f1);
    float d1 = __fsub_rn(c1, f1);
    float h1 = __fsub_rn(c1, d1);
    float l1 = __fsub_rn(f1, h1);
    h = cvtH2(h0, h1);
    l = cvtH2(l0, l1);
}
DI void hmma(float* c, const u32* a, u32 b0, u32 b1) {
    asm("mma.sync.aligned.m16n8k16.row.col.f32.f16.f16.f32 "
        "{%0,%1,%2,%3},{%4,%5,%6,%7},{%8,%9},{%0,%1,%2,%3};"
        : "+f"(c[0]), "+f"(c[1]), "+f"(c[2]), "+f"(c[3])
        : "r"(a[0]), "r"(a[1]), "r"(a[2]), "r"(a[3]), "r"(b0), "r"(b1));
}

// ------------------------- global scratch ----------------------------------
// B=4 T=64 N=32 M=32 D=128 ; BT=256 ; units=2048 ; bands=16384 (16 rows each)
__device__ __align__(16) float g_p [8192 * 128];   // p[row][d]   row=bt*32+n
__device__ __align__(16) float g_A [8192 * 128];   // A[row][k]
__device__ __align__(16) float g_v [8192 * 128];   // v[row][d]   row=bt*32+m
__device__ __align__(16) float g_Bv[8192 * 128];   // Bv[row][k]  (b1 folded)
// fp16 images: [mat][n][sj] uint2 { h(k0,k1), h(k8,k9) }
// mat: 0 Wc, 1 Wd, 2 W2, 3 W_p, 4 W_v, 5 W1p, 6 W1v ; sj = 4s+j ; k0 = 16s+2j
#define IMG2_S 36                   // uint2 stride per n (conflict-free LDS.64)
#define IMG2   (128 * IMG2_S)       // 4608 uint2 per image (36,864 B)
__device__ __align__(16) uint2 g_img2[7 * IMG2];

// ---------------------------------------------------------------------------
// Kernel 1: weight prep (fp16 round) into images. grid (7,16) x 256.
// ---------------------------------------------------------------------------
__global__ void __launch_bounds__(256) k_wprep(const float* __restrict__ W_p,
                                               const float* __restrict__ W_v,
                                               const float* __restrict__ W1,
                                               const float* __restrict__ W2)
{
    const int mat = blockIdx.x;
    const float* src =
        (mat == 0) ? (W1 + 256 * 128) :
        (mat == 1) ? (W1 + 384 * 128) :
        (mat == 2) ? W2 :
        (mat == 3) ? W_p :
        (mat == 4) ? W_v :
        (mat == 5) ? W1 : (W1 + 128 * 128);
    const int pos = blockIdx.y * 256 + threadIdx.x;   // 0..4095
    const int n  = pos & 127;
    const int sj = pos >> 7;
    const int s  = sj >> 2, j = sj & 3;
    const int ka = 16 * s + 2 * j;
    u32 h0 = cvtH2(__ldg(src + ka * 128 + n),       __ldg(src + (ka + 1) * 128 + n));
    u32 h1 = cvtH2(__ldg(src + (ka + 8) * 128 + n), __ldg(src + (ka + 9) * 128 + n));
    g_img2[mat * IMG2 + n * IMG2_S + sj] = make_uint2(h0, h1);
}

// ---------------------------------------------------------------------------
// Kernel 2: HMMA precompute of p, v, A, Bv. grid (128, 2) x 128 thr, 2 CTA/SM.
// Block = 64 rows of one path; warp = 16 rows x 128 cols. Weights via __ldg
// streams (no smem, no barriers). 2-pass fp16, depth-8 interleave.
// ---------------------------------------------------------------------------
__global__ void __launch_bounds__(128, 2) k_pre_mma(
    const float* __restrict__ price, const float* __restrict__ liquid,
    const float* __restrict__ b_p,   const float* __restrict__ b_v,
    const float* __restrict__ b1)
{
    const int path = blockIdx.y;
    const int r0   = blockIdx.x * 64;
    const float* X  = path ? liquid : price;
    const float* bi = path ? b_v : b_p;
    const uint2* imgW  = g_img2 + (3 + path) * IMG2;   // W_p / W_v
    const uint2* imgW1 = g_img2 + (5 + path) * IMG2;   // W1p / W1v
    float* dstY = path ? g_v  : g_p;
    float* dstZ = path ? g_Bv : g_A;

    const int tid  = threadIdx.x;
    const int w    = tid >> 5;
    const int lane = tid & 31;
    const int g    = lane >> 2;
    const int j    = lane & 3;

    // ---- load X A-fragments (fp16 Veltkamp split) ----
    const int ra = r0 + w * 16 + g;
    const int rb = ra + 8;
    u32 Xh[8][4], Xl[8][4];
#pragma unroll
    for (int s = 0; s < 8; s++) {
        const int ka = 16 * s + 2 * j;
        float2 xa0 = *(const float2*)(X + (size_t)ra * 128 + ka);
        float2 xb0 = *(const float2*)(X + (size_t)rb * 128 + ka);
        float2 xa1 = *(const float2*)(X + (size_t)ra * 128 + ka + 8);
        float2 xb1 = *(const float2*)(X + (size_t)rb * 128 + ka + 8);
        splitH2(xa0.x, xa0.y, Xh[s][0], Xl[s][0]);
        splitH2(xb0.x, xb0.y, Xh[s][1], Xl[s][1]);
        splitH2(xa1.x, xa1.y, Xh[s][2], Xl[s][2]);
        splitH2(xb1.x, xb1.y, Xh[s][3], Xl[s][3]);
    }

    // ---- GEMM1: Y = X @ Wi (2-pass, depth-8) ----
    float yacc[16][4];
#pragma unroll
    for (int nt = 0; nt < 16; nt++)
#pragma unroll
        for (int q = 0; q < 4; q++) yacc[nt][q] = 0.0f;
#pragma unroll
    for (int s = 0; s < 8; s++)
#pragma unroll
        for (int q = 0; q < 2; q++) {
            uint2 wv[8];
#pragma unroll
            for (int t = 0; t < 8; t++)
                wv[t] = __ldg(imgW + (8 * (8 * q + t) + g) * IMG2_S + 4 * s + j);
#pragma unroll
            for (int t = 0; t < 8; t++) hmma(yacc[8 * q + t], Xh[s], wv[t].x, wv[t].y);
#pragma unroll
            for (int t = 0; t < 8; t++) hmma(yacc[8 * q + t], Xl[s], wv[t].x, wv[t].y);
        }

    // ---- epilogue 1: + bias, store Y, re-split as GEMM2 A-frags ----
#pragma unroll
    for (int nt = 0; nt < 16; nt++) {
        const int c = 8 * nt + 2 * j;
        const float bb0 = __ldg(bi + c), bb1 = __ldg(bi + c + 1);
        float y0 = yacc[nt][0] + bb0, y1 = yacc[nt][1] + bb1;
        float y2 = yacc[nt][2] + bb0, y3 = yacc[nt][3] + bb1;
        *(float2*)(dstY + (size_t)ra * 128 + c) = make_float2(y0, y1);
        *(float2*)(dstY + (size_t)rb * 128 + c) = make_float2(y2, y3);
        const int s2 = nt >> 1, o = (nt & 1) * 2;
        splitH2(y0, y1, Xh[s2][o],     Xl[s2][o]);
        splitH2(y2, y3, Xh[s2][o + 1], Xl[s2][o + 1]);
    }

    // ---- GEMM2: Z = Y @ W1x (2-pass, depth-8) ----
    float zacc[16][4];
#pragma unroll
    for (int nt = 0; nt < 16; nt++)
#pragma unroll
        for (int q = 0; q < 4; q++) zacc[nt][q] = 0.0f;
#pragma unroll
    for (int s = 0; s < 8; s++)
#pragma unroll
        for (int q = 0; q < 2; q++) {
            uint2 wv[8];
#pragma unroll
            for (int t = 0; t < 8; t++)
                wv[t] = __ldg(imgW1 + (8 * (8 * q + t) + g) * IMG2_S + 4 * s + j);
#pragma unroll
            for (int t = 0; t < 8; t++) hmma(zacc[8 * q + t], Xh[s], wv[t].x, wv[t].y);
#pragma unroll
            for (int t = 0; t < 8; t++) hmma(zacc[8 * q + t], Xl[s], wv[t].x, wv[t].y);
        }

    // ---- epilogue 2: (+ b1 on liquid path), store Z ----
#pragma unroll
    for (int nt = 0; nt < 16; nt++) {
        const int c = 8 * nt + 2 * j;
        const float bb0 = path ? __ldg(b1 + c)     : 0.0f;
        const float bb1 = path ? __ldg(b1 + c + 1) : 0.0f;
        *(float2*)(dstZ + (size_t)ra * 128 + c) =
            make_float2(zacc[nt][0] + bb0, zacc[nt][1] + bb1);
        *(float2*)(dstZ + (size_t)rb * 128 + c) =
            make_float2(zacc[nt][2] + bb0, zacc[nt][3] + bb1);
    }
}

// ---------------------------------------------------------------------------
// Kernel 3: pair kernel — 148 x 256 thr, 8 independent warps/CTA.
// Band = 16 pair-rows x 128 cols; 16384 bands over 1184 warps, contiguous.
// smem: Wc+Wd+W2 fp16 images (110.6 KB) + b2 ; v/Bv/p/A via L1 __ldg.
// 2-pass fp16 (Veltkamp split), depth-8 interleave, no loop barriers.
// ---------------------------------------------------------------------------
__global__ void __launch_bounds__(256, 1) k_pair_mma(const float* __restrict__ b2,
                                                     float* __restrict__ out)
{
    extern __shared__ __align__(16) char smem[];
    uint2* sC  = (uint2*)smem;                      // Wc
    uint2* sD  = sC + IMG2;                         // Wd
    uint2* sW2 = sD + IMG2;                         // W2
    float* sB2 = (float*)(sW2 + IMG2);              // [128]

    const int tid  = threadIdx.x;
    const int w    = tid >> 5;
    const int lane = tid & 31;
    const int g    = lane >> 2;
    const int j    = lane & 3;

    for (int i = tid; i < 3 * IMG2; i += 256) ((uint2*)sC)[i] = g_img2[i];
    for (int i = tid; i < 128; i += 256) sB2[i] = b2[i];
    __syncthreads();

    const int gw   = blockIdx.x * 8 + w;            // 0..1183
    const int b_lo = (int)(((long long)gw * 16384) / 1184);
    const int b_hi = (int)(((long long)(gw + 1) * 16384) / 1184);

    for (int b = b_lo; b < b_hi; b++) {
        const int bt   = b >> 6;
        const int tile = (b >> 3) & 7;
        const int rb   = b & 7;
        const int ln   = rb >> 1;
        const int mlo  = (rb & 1) * 16 + g;
        const int mhi  = mlo + 8;
        const float* prow = g_p  + (size_t)(bt * 32 + tile * 4 + ln) * 128;
        const float* arow = g_A  + (size_t)(bt * 32 + tile * 4 + ln) * 128;
        const float* vlo  = g_v  + (size_t)(bt * 32 + mlo) * 128;
        const float* vhi  = g_v  + (size_t)(bt * 32 + mhi) * 128;
        const float* bvlo = g_Bv + (size_t)(bt * 32 + mlo) * 128;
        const float* bvhi = g_Bv + (size_t)(bt * 32 + mhi) * 128;

        // ---- layer 1: acc = (p*v)@Wc + |p-v|@Wd (2-pass, depth-8) ----
        float acc[16][4];
#pragma unroll
        for (int nt = 0; nt < 16; nt++)
#pragma unroll
            for (int q = 0; q < 4; q++) acc[nt][q] = 0.0f;

#pragma unroll
        for (int s = 0; s < 8; s++) {
            const int d0 = 16 * s + 2 * j;
            float2 pa  = *(const float2*)(prow + d0);
            float2 pb  = *(const float2*)(prow + d0 + 8);
            float2 va0 = __ldg((const float2*)(vlo + d0));
            float2 vb0 = __ldg((const float2*)(vhi + d0));
            float2 va8 = __ldg((const float2*)(vlo + d0 + 8));
            float2 vb8 = __ldg((const float2*)(vhi + d0 + 8));
            u32 Ph[4], Pl[4], Qh[4], Ql[4];
            splitH2(pa.x * va0.x, pa.y * va0.y, Ph[0], Pl[0]);
            splitH2(pa.x * vb0.x, pa.y * vb0.y, Ph[1], Pl[1]);
            splitH2(pb.x * va8.x, pb.y * va8.y, Ph[2], Pl[2]);
            splitH2(pb.x * vb8.x, pb.y * vb8.y, Ph[3], Pl[3]);
            splitH2(fabsf(pa.x - va0.x), fabsf(pa.y - va0.y), Qh[0], Ql[0]);
            splitH2(fabsf(pa.x - vb0.x), fabsf(pa.y - vb0.y), Qh[1], Ql[1]);
            splitH2(fabsf(pb.x - va8.x), fabsf(pb.y - va8.y), Qh[2], Ql[2]);
            splitH2(fabsf(pb.x - vb8.x), fabsf(pb.y - vb8.y), Qh[3], Ql[3]);
#pragma unroll
            for (int q = 0; q < 2; q++) {
                uint2 cv[8];
#pragma unroll
                for (int t = 0; t < 8; t++)
                    cv[t] = sC[(8 * (8 * q + t) + g) * IMG2_S + 4 * s + j];
#pragma unroll
                for (int t = 0; t < 8; t++) hmma(acc[8 * q + t], Ph, cv[t].x, cv[t].y);
#pragma unroll
                for (int t = 0; t < 8; t++) hmma(acc[8 * q + t], Pl, cv[t].x, cv[t].y);
                uint2 dv[8];
#pragma unroll
                for (int t = 0; t < 8; t++)
                    dv[t] = sD[(8 * (8 * q + t) + g) * IMG2_S + 4 * s + j];
#pragma unroll
                for (int t = 0; t < 8; t++) hmma(acc[8 * q + t], Qh, dv[t].x, dv[t].y);
#pragma unroll
                for (int t = 0; t < 8; t++) hmma(acc[8 * q + t], Ql, dv[t].x, dv[t].y);
            }
        }

        // ---- epilogue 1: z = acc + A + Bv ; H = silu(z) as reg A-frags ----
        u32 Hh[8][4], Hl[8][4];
#pragma unroll
        for (int nt = 0; nt < 16; nt++) {
            int col = 8 * nt + 2 * j;
            float2 a2 = *(const float2*)(arow + col);
            float2 bl = __ldg((const float2*)(bvlo + col));
            float2 bh = __ldg((const float2*)(bvhi + col));
            float z0 = acc[nt][0] + a2.x + bl.x;
            float z1 = acc[nt][1] + a2.y + bl.y;
            float z2 = acc[nt][2] + a2.x + bh.x;
            float z3 = acc[nt][3] + a2.y + bh.y;
            int s2 = nt >> 1, o = (nt & 1) * 2;
            splitH2(silu_f(z0), silu_f(z1), Hh[s2][o],     Hl[s2][o]);
            splitH2(silu_f(z2), silu_f(z3), Hh[s2][o + 1], Hl[s2][o + 1]);
        }

        // ---- layer 2: out = H @ W2 (2-pass, depth-8, smem) ----
        float ac2[16][4];
#pragma unroll
        for (int nt = 0; nt < 16; nt++)
#pragma unroll
            for (int q = 0; q < 4; q++) ac2[nt][q] = 0.0f;

#pragma unroll
        for (int s = 0; s < 8; s++)
#pragma unroll
            for (int q = 0; q < 2; q++) {
                uint2 wv[8];
#pragma unroll
                for (int t = 0; t < 8; t++)
                    wv[t] = sW2[(8 * (8 * q + t) + g) * IMG2_S + 4 * s + j];
#pragma unroll
                for (int t = 0; t < 8; t++) hmma(ac2[8 * q + t], Hh[s], wv[t].x, wv[t].y);
#pragma unroll
                for (int t = 0; t < 8; t++) hmma(ac2[8 * q + t], Hl[s], wv[t].x, wv[t].y);
            }

        // ---- epilogue 2: + b2, store ----
        const int u = bt * 8 + tile;
        float* ob = out + ((size_t)u * 128 + ln * 32) * 128;
#pragma unroll
        for (int nt = 0; nt < 16; nt++) {
            int col = 8 * nt + 2 * j;
            float bb0 = sB2[col], bb1 = sB2[col + 1];
            *(float2*)(ob + (size_t)mlo * 128 + col) =
                make_float2(ac2[nt][0] + bb0, ac2[nt][1] + bb1);
            *(float2*)(ob + (size_t)mhi * 128 + col) =
                make_float2(ac2[nt][2] + bb0, ac2[nt][3] + bb1);
        }
    }
}

// ---------------------------------------------------------------------------
extern "C" void kernel_launch(void* const* d_in, const int* in_sizes, int n_in,
                              void* d_out, int out_size)
{
    const float* price  = (const float*)d_in[0];
    const float* liquid = (const float*)d_in[1];
    const float* W_p = (const float*)d_in[2];
    const float* b_p = (const float*)d_in[3];
    const float* W_v = (const float*)d_in[4];
    const float* b_v = (const float*)d_in[5];
    const float* W1  = (const float*)d_in[6];
    const float* b1  = (const float*)d_in[7];
    const float* W2  = (const float*)d_in[8];
    const float* b2  = (const float*)d_in[9];
    float* out = (float*)d_out;

    const size_t sm2 = 3 * IMG2 * 8 + 128 * 4;        // 111,104
    cudaFuncSetAttribute(k_pair_mma, cudaFuncAttributeMaxDynamicSharedMemorySize, (int)sm2);

    k_wprep<<<dim3(7, 16), 256>>>(W_p, W_v, W1, W2);
    k_pre_mma<<<dim3(128, 2), 128>>>(price, liquid, b_p, b_v, b1);
    k_pair_mma<<<148, 256, sm2>>>(b2, out);
}

// round 16
// speedup vs baseline: 1.8579x; 1.2926x over previous
#include <cuda_runtime.h>
#include <cuda_fp16.h>
#include <cstdint>

// ---------------------------------------------------------------------------
// PairInteractionGrid (sm_103a) R13 — single-pass fp16 HMMA (fp32 accumulate).
//   All operands rounded once to fp16; no hi/lo splits.
//   Calibrated error model: 10 dropped residual terms x 1.6e-4 -> ~5e-4 rel.
//   p  = price @ W_p + b_p ; v = liquid @ W_v + b_v          (k_pre)
//   A  = p @ W1p ; Bv = v @ W1v + b1                          (k_pre)
//   z(n,m) = A_n + Bv_m + (p*v)@Wc + |p-v|@Wd                 (k_pair)
//   out = silu(z) @ W2 + b2                                   (k_pair)
// ---------------------------------------------------------------------------

typedef unsigned int u32;
#define DI __device__ __forceinline__

DI float silu_f(float x) { return __fdividef(x, 1.0f + __expf(-x)); }

DI u32 cvtH2(float f0, float f1) {   // f0 -> low half fp16x2
    u32 r; asm("cvt.rn.f16x2.f32 %0, %1, %2;" : "=r"(r) : "f"(f1), "f"(f0)); return r;
}
DI void hmma(float* c, const u32* a, u32 b0, u32 b1) {
    asm("mma.sync.aligned.m16n8k16.row.col.f32.f16.f16.f32 "
        "{%0,%1,%2,%3},{%4,%5,%6,%7},{%8,%9},{%0,%1,%2,%3};"
        : "+f"(c[0]), "+f"(c[1]), "+f"(c[2]), "+f"(c[3])
        : "r"(a[0]), "r"(a[1]), "r"(a[2]), "r"(a[3]), "r"(b0), "r"(b1));
}

// ------------------------- global scratch ----------------------------------
// B=4 T=64 N=32 M=32 D=128 ; BT=256 ; units=2048 ; bands=16384 (16 rows each)
__device__ __align__(16) float g_p [8192 * 128];   // p[row][d]   row=bt*32+n
__device__ __align__(16) float g_A [8192 * 128];   // A[row][k]
__device__ __align__(16) float g_v [8192 * 128];   // v[row][d]   row=bt*32+m
__device__ __align__(16) float g_Bv[8192 * 128];   // Bv[row][k]  (b1 folded)
// fp16 images: [mat][n][sj] uint2 { h(k0,k1), h(k8,k9) }
// mat: 0 Wc, 1 Wd, 2 W2, 3 W_p, 4 W_v, 5 W1p, 6 W1v ; sj = 4s+j ; k0 = 16s+2j
#define IMG2_S 36                   // uint2 stride per n (conflict-free LDS.64)
#define IMG2   (128 * IMG2_S)       // 4608 uint2 per image (36,864 B)
__device__ __align__(16) uint2 g_img2[7 * IMG2];

// ---------------------------------------------------------------------------
// Kernel 1: weight prep (fp16 round) into images. grid (7,16) x 256.
// ---------------------------------------------------------------------------
__global__ void __launch_bounds__(256) k_wprep(const float* __restrict__ W_p,
                                               const float* __restrict__ W_v,
                                               const float* __restrict__ W1,
                                               const float* __restrict__ W2)
{
    const int mat = blockIdx.x;
    const float* src =
        (mat == 0) ? (W1 + 256 * 128) :
        (mat == 1) ? (W1 + 384 * 128) :
        (mat == 2) ? W2 :
        (mat == 3) ? W_p :
        (mat == 4) ? W_v :
        (mat == 5) ? W1 : (W1 + 128 * 128);
    const int pos = blockIdx.y * 256 + threadIdx.x;   // 0..4095
    const int n  = pos & 127;
    const int sj = pos >> 7;
    const int s  = sj >> 2, j = sj & 3;
    const int ka = 16 * s + 2 * j;
    u32 h0 = cvtH2(__ldg(src + ka * 128 + n),       __ldg(src + (ka + 1) * 128 + n));
    u32 h1 = cvtH2(__ldg(src + (ka + 8) * 128 + n), __ldg(src + (ka + 9) * 128 + n));
    g_img2[mat * IMG2 + n * IMG2_S + sj] = make_uint2(h0, h1);
}

// ---------------------------------------------------------------------------
// Kernel 2: HMMA precompute of p, v, A, Bv. grid (128, 2) x 128 thr, 2 CTA/SM.
// Block = 64 rows of one path; warp = 16 rows x 128 cols. Weights via __ldg
// streams (no smem, no barriers). Single-pass fp16, depth-8 interleave.
// ---------------------------------------------------------------------------
__global__ void __launch_bounds__(128, 2) k_pre_mma(
    const float* __restrict__ price, const float* __restrict__ liquid,
    const float* __restrict__ b_p,   const float* __restrict__ b_v,
    const float* __restrict__ b1)
{
    const int path = blockIdx.y;
    const int r0   = blockIdx.x * 64;
    const float* X  = path ? liquid : price;
    const float* bi = path ? b_v : b_p;
    const uint2* imgW  = g_img2 + (3 + path) * IMG2;   // W_p / W_v
    const uint2* imgW1 = g_img2 + (5 + path) * IMG2;   // W1p / W1v
    float* dstY = path ? g_v  : g_p;
    float* dstZ = path ? g_Bv : g_A;

    const int tid  = threadIdx.x;
    const int w    = tid >> 5;
    const int lane = tid & 31;
    const int g    = lane >> 2;
    const int j    = lane & 3;

    // ---- load X A-fragments (fp16 round) ----
    const int ra = r0 + w * 16 + g;
    const int rb = ra + 8;
    u32 Xh[8][4];
#pragma unroll
    for (int s = 0; s < 8; s++) {
        const int ka = 16 * s + 2 * j;
        float2 xa0 = *(const float2*)(X + (size_t)ra * 128 + ka);
        float2 xb0 = *(const float2*)(X + (size_t)rb * 128 + ka);
        float2 xa1 = *(const float2*)(X + (size_t)ra * 128 + ka + 8);
        float2 xb1 = *(const float2*)(X + (size_t)rb * 128 + ka + 8);
        Xh[s][0] = cvtH2(xa0.x, xa0.y);
        Xh[s][1] = cvtH2(xb0.x, xb0.y);
        Xh[s][2] = cvtH2(xa1.x, xa1.y);
        Xh[s][3] = cvtH2(xb1.x, xb1.y);
    }

    // ---- GEMM1: Y = X @ Wi (single-pass, depth-8) ----
    float yacc[16][4];
#pragma unroll
    for (int nt = 0; nt < 16; nt++)
#pragma unroll
        for (int q = 0; q < 4; q++) yacc[nt][q] = 0.0f;
#pragma unroll
    for (int s = 0; s < 8; s++)
#pragma unroll
        for (int q = 0; q < 2; q++) {
            uint2 wv[8];
#pragma unroll
            for (int t = 0; t < 8; t++)
                wv[t] = __ldg(imgW + (8 * (8 * q + t) + g) * IMG2_S + 4 * s + j);
#pragma unroll
            for (int t = 0; t < 8; t++) hmma(yacc[8 * q + t], Xh[s], wv[t].x, wv[t].y);
        }

    // ---- epilogue 1: + bias, store Y, re-round as GEMM2 A-frags ----
#pragma unroll
    for (int nt = 0; nt < 16; nt++) {
        const int c = 8 * nt + 2 * j;
        const float bb0 = __ldg(bi + c), bb1 = __ldg(bi + c + 1);
        float y0 = yacc[nt][0] + bb0, y1 = yacc[nt][1] + bb1;
        float y2 = yacc[nt][2] + bb0, y3 = yacc[nt][3] + bb1;
        *(float2*)(dstY + (size_t)ra * 128 + c) = make_float2(y0, y1);
        *(float2*)(dstY + (size_t)rb * 128 + c) = make_float2(y2, y3);
        const int s2 = nt >> 1, o = (nt & 1) * 2;
        Xh[s2][o]     = cvtH2(y0, y1);
        Xh[s2][o + 1] = cvtH2(y2, y3);
    }

    // ---- GEMM2: Z = Y @ W1x (single-pass, depth-8) ----
    float zacc[16][4];
#pragma unroll
    for (int nt = 0; nt < 16; nt++)
#pragma unroll
        for (int q = 0; q < 4; q++) zacc[nt][q] = 0.0f;
#pragma unroll
    for (int s = 0; s < 8; s++)
#pragma unroll
        for (int q = 0; q < 2; q++) {
            uint2 wv[8];
#pragma unroll
            for (int t = 0; t < 8; t++)
                wv[t] = __ldg(imgW1 + (8 * (8 * q + t) + g) * IMG2_S + 4 * s + j);
#pragma unroll
            for (int t = 0; t < 8; t++) hmma(zacc[8 * q + t], Xh[s], wv[t].x, wv[t].y);
        }

    // ---- epilogue 2: (+ b1 on liquid path), store Z ----
#pragma unroll
    for (int nt = 0; nt < 16; nt++) {
        const int c = 8 * nt + 2 * j;
        const float bb0 = path ? __ldg(b1 + c)     : 0.0f;
        const float bb1 = path ? __ldg(b1 + c + 1) : 0.0f;
        *(float2*)(dstZ + (size_t)ra * 128 + c) =
            make_float2(zacc[nt][0] + bb0, zacc[nt][1] + bb1);
        *(float2*)(dstZ + (size_t)rb * 128 + c) =
            make_float2(zacc[nt][2] + bb0, zacc[nt][3] + bb1);
    }
}

// ---------------------------------------------------------------------------
// Kernel 3: pair kernel — 148 x 256 thr, 8 independent warps/CTA.
// Band = 16 pair-rows x 128 cols; 16384 bands over 1184 warps, contiguous.
// smem: Wc+Wd+W2 fp16 images (110.6 KB) + b2 ; v/Bv/p/A via L1 __ldg.
// Single-pass fp16, depth-8 interleave, no loop barriers.
// ---------------------------------------------------------------------------
__global__ void __launch_bounds__(256, 1) k_pair_mma(const float* __restrict__ b2,
                                                     float* __restrict__ out)
{
    extern __shared__ __align__(16) char smem[];
    uint2* sC  = (uint2*)smem;                      // Wc
    uint2* sD  = sC + IMG2;                         // Wd
    uint2* sW2 = sD + IMG2;                         // W2
    float* sB2 = (float*)(sW2 + IMG2);              // [128]

    const int tid  = threadIdx.x;
    const int w    = tid >> 5;
    const int lane = tid & 31;
    const int g    = lane >> 2;
    const int j    = lane & 3;

    for (int i = tid; i < 3 * IMG2; i += 256) ((uint2*)sC)[i] = g_img2[i];
    for (int i = tid; i < 128; i += 256) sB2[i] = b2[i];
    __syncthreads();

    const int gw   = blockIdx.x * 8 + w;            // 0..1183
    const int b_lo = (int)(((long long)gw * 16384) / 1184);
    const int b_hi = (int)(((long long)(gw + 1) * 16384) / 1184);

    for (int b = b_lo; b < b_hi; b++) {
        const int bt   = b >> 6;
        const int tile = (b >> 3) & 7;
        const int rb   = b & 7;
        const int ln   = rb >> 1;
        const int mlo  = (rb & 1) * 16 + g;
        const int mhi  = mlo + 8;
        const float* prow = g_p  + (size_t)(bt * 32 + tile * 4 + ln) * 128;
        const float* arow = g_A  + (size_t)(bt * 32 + tile * 4 + ln) * 128;
        const float* vlo  = g_v  + (size_t)(bt * 32 + mlo) * 128;
        const float* vhi  = g_v  + (size_t)(bt * 32 + mhi) * 128;
        const float* bvlo = g_Bv + (size_t)(bt * 32 + mlo) * 128;
        const float* bvhi = g_Bv + (size_t)(bt * 32 + mhi) * 128;

        // ---- layer 1: acc = (p*v)@Wc + |p-v|@Wd (single-pass, depth-8) ----
        float acc[16][4];
#pragma unroll
        for (int nt = 0; nt < 16; nt++)
#pragma unroll
            for (int q = 0; q < 4; q++) acc[nt][q] = 0.0f;

#pragma unroll
        for (int s = 0; s < 8; s++) {
            const int d0 = 16 * s + 2 * j;
            float2 pa  = *(const float2*)(prow + d0);
            float2 pb  = *(const float2*)(prow + d0 + 8);
            float2 va0 = __ldg((const float2*)(vlo + d0));
            float2 vb0 = __ldg((const float2*)(vhi + d0));
            float2 va8 = __ldg((const float2*)(vlo + d0 + 8));
            float2 vb8 = __ldg((const float2*)(vhi + d0 + 8));
            u32 Ph[4], Qh[4];
            Ph[0] = cvtH2(pa.x * va0.x, pa.y * va0.y);
            Ph[1] = cvtH2(pa.x * vb0.x, pa.y * vb0.y);
            Ph[2] = cvtH2(pb.x * va8.x, pb.y * va8.y);
            Ph[3] = cvtH2(pb.x * vb8.x, pb.y * vb8.y);
            Qh[0] = cvtH2(fabsf(pa.x - va0.x), fabsf(pa.y - va0.y));
            Qh[1] = cvtH2(fabsf(pa.x - vb0.x), fabsf(pa.y - vb0.y));
            Qh[2] = cvtH2(fabsf(pb.x - va8.x), fabsf(pb.y - va8.y));
            Qh[3] = cvtH2(fabsf(pb.x - vb8.x), fabsf(pb.y - vb8.y));
#pragma unroll
            for (int q = 0; q < 2; q++) {
                uint2 cv[8];
#pragma unroll
                for (int t = 0; t < 8; t++)
                    cv[t] = sC[(8 * (8 * q + t) + g) * IMG2_S + 4 * s + j];
#pragma unroll
                for (int t = 0; t < 8; t++) hmma(acc[8 * q + t], Ph, cv[t].x, cv[t].y);
                uint2 dv[8];
#pragma unroll
                for (int t = 0; t < 8; t++)
                    dv[t] = sD[(8 * (8 * q + t) + g) * IMG2_S + 4 * s + j];
#pragma unroll
                for (int t = 0; t < 8; t++) hmma(acc[8 * q + t], Qh, dv[t].x, dv[t].y);
            }
        }

        // ---- epilogue 1: z = acc + A + Bv ; H = fp16(silu(z)) A-frags ----
        u32 Hh[8][4];
#pragma unroll
        for (int nt = 0; nt < 16; nt++) {
            int col = 8 * nt + 2 * j;
            float2 a2 = *(const float2*)(arow + col);
            float2 bl = __ldg((const float2*)(bvlo + col));
            float2 bh = __ldg((const float2*)(bvhi + col));
            float z0 = acc[nt][0] + a2.x + bl.x;
            float z1 = acc[nt][1] + a2.y + bl.y;
            float z2 = acc[nt][2] + a2.x + bh.x;
            float z3 = acc[nt][3] + a2.y + bh.y;
            int s2 = nt >> 1, o = (nt & 1) * 2;
            Hh[s2][o]     = cvtH2(silu_f(z0), silu_f(z1));
            Hh[s2][o + 1] = cvtH2(silu_f(z2), silu_f(z3));
        }

        // ---- layer 2: out = H @ W2 (single-pass, depth-8, smem) ----
        float ac2[16][4];
#pragma unroll
        for (int nt = 0; nt < 16; nt++)
#pragma unroll
            for (int q = 0; q < 4; q++) ac2[nt][q] = 0.0f;

#pragma unroll
        for (int s = 0; s < 8; s++)
#pragma unroll
            for (int q = 0; q < 2; q++) {
                uint2 wv[8];
#pragma unroll
                for (int t = 0; t < 8; t++)
                    wv[t] = sW2[(8 * (8 * q + t) + g) * IMG2_S + 4 * s + j];
#pragma unroll
                for (int t = 0; t < 8; t++) hmma(ac2[8 * q + t], Hh[s], wv[t].x, wv[t].y);
            }

        // ---- epilogue 2: + b2, store ----
        const int u = bt * 8 + tile;
        float* ob = out + ((size_t)u * 128 + ln * 32) * 128;
#pragma unroll
        for (int nt = 0; nt < 16; nt++) {
            int col = 8 * nt + 2 * j;
            float bb0 = sB2[col], bb1 = sB2[col + 1];
            *(float2*)(ob + (size_t)mlo * 128 + col) =
                make_float2(ac2[nt][0] + bb0, ac2[nt][1] + bb1);
            *(float2*)(ob + (size_t)mhi * 128 + col) =
                make_float2(ac2[nt][2] + bb0, ac2[nt][3] + bb1);
        }
    }
}

// ---------------------------------------------------------------------------
extern "C" void kernel_launch(void* const* d_in, const int* in_sizes, int n_in,
                              void* d_out, int out_size)
{
    const float* price  = (const float*)d_in[0];
    const float* liquid = (const float*)d_in[1];
    const float* W_p = (const float*)d_in[2];
    const float* b_p = (const float*)d_in[3];
    const float* W_v = (const float*)d_in[4];
    const float* b_v = (const float*)d_in[5];
    const float* W1  = (const float*)d_in[6];
    const float* b1  = (const float*)d_in[7];
    const float* W2  = (const float*)d_in[8];
    const float* b2  = (const float*)d_in[9];
    float* out = (float*)d_out;

    const size_t sm2 = 3 * IMG2 * 8 + 128 * 4;        // 111,104
    cudaFuncSetAttribute(k_pair_mma, cudaFuncAttributeMaxDynamicSharedMemorySize, (int)sm2);

    k_wprep<<<dim3(7, 16), 256>>>(W_p, W_v, W1, W2);
    k_pre_mma<<<dim3(128, 2), 128>>>(price, liquid, b_p, b_v, b1);
    k_pair_mma<<<148, 256, sm2>>>(b2, out);
}